// round 14
// baseline (speedup 1.0000x reference)
#include <cuda_runtime.h>
#include <cuda_bf16.h>
#include <math.h>

#define KC 64
#define DD 128
#define NN 4096
#define NB 32
#define NT 512
#define GRID (NN / NB)   // 128 blocks: one per SM, single balanced wave
#define MPAD 132         // 16B-aligned rows; LDS.128 phases conflict-free

#define LN2F 0.6931471805599453f
#define LOG2PIF 1.8378770664093453f
#define LGAMMA64F 201.00931639928152f

// ---------------- device scratch (zero-init; self-resetting each run) ----------------
__device__ __align__(16) float g_numer[KC * KC];   // sum of (ln2 - softplus)
__device__ __align__(16) float g_dsum[KC * KC];    // sum over class i of kap_j*(fhat.mu_j)
__device__ float g_counts[KC];
__device__ int   g_arrive;

__device__ __forceinline__ float softplus_precise(float x) {
    return (x > 0.0f) ? (x + log1pf(expf(-x))) : log1pf(expf(x));
}

// log1p(t), t in [0,1]: Taylor at t=0.5, deg 11, |err| < 2e-7. Pure FFMA.
__device__ __forceinline__ float log1p_poly(float t) {
    float s = t - 0.5f;
    float p = -0.0017337974f + 0.0010507863f * s;
    p = fmaf(p, s,  0.0028896624f);
    p = fmaf(p, s, -0.0048773053f);
    p = fmaf(p, s,  0.0083610948f);
    p = fmaf(p, s, -0.0146319159f);
    p = fmaf(p, s,  0.0263374486f);
    p = fmaf(p, s, -0.0493827160f);
    p = fmaf(p, s,  0.0987654321f);
    p = fmaf(p, s, -0.2222222222f);
    p = fmaf(p, s,  0.6666666667f);
    p = fmaf(p, s,  0.4054651081f);
    return p;
}

__device__ __forceinline__ void red_v4(float* gptr, float a, float b, float c, float d) {
    unsigned long long ga = (unsigned long long)__cvta_generic_to_global(gptr);
    asm volatile("red.global.add.v4.f32 [%0], {%1, %2, %3, %4};"
                 :: "l"(ga), "f"(a), "f"(b), "f"(c), "f"(d) : "memory");
}

// packed dual-FMA: d = a*b + d on two f32 lanes (sm_100+)
__device__ __forceinline__ void fma2(unsigned long long& d,
                                     unsigned long long a, unsigned long long b) {
    asm("fma.rn.f32x2 %0, %1, %2, %0;" : "+l"(d) : "l"(a), "l"(b));
}
__device__ __forceinline__ float hsum2(unsigned long long v) {
    float lo, hi;
    asm("mov.b64 {%0, %1}, %2;" : "=f"(lo), "=f"(hi) : "l"(v));
    return lo + hi;
}

struct __align__(16) Smem {
    float mus[KC * MPAD];        // raw mus, 16B-aligned rows — epilogue dsum overlay
    float f[NB][DD];             // features (16KB) — epilogue numer overlay
    float L[NB][KC];             // logits (8KB)    — epilogue scratch
    float lc[KC];
    float invmu[KC], kap[KC];
    float invn[NB];
    float musq[8][KC];
    int   lab[NB];
    int   is_last;
};

__global__ void __launch_bounds__(NT, 1) k_fused(const float* __restrict__ feat,
                                                 const float* __restrict__ musp,
                                                 const float* __restrict__ rho,
                                                 const int* __restrict__ lab32,
                                                 float* __restrict__ out) {
    extern __shared__ char smem_raw[];
    Smem* s = (Smem*)smem_raw;
    int tid = threadIdx.x;
    int bid = blockIdx.x;
    int n0 = bid * NB;

    // labels dtype probe (odd int32 words nonzero => int32 labels)
    int pred = (lab32[2 * tid + 1] != 0);

    // load mus_param coalesced -> padded rows
    {
        const float4* msrc = (const float4*)musp;
#pragma unroll
        for (int r = 0; r < 4; r++) {
            int idx = tid + NT * r;
            float4 v = msrc[idx];
            int k = idx >> 5, d = (idx & 31) * 4;
            float* p = &s->mus[k * MPAD + d];
            p[0] = v.x; p[1] = v.y; p[2] = v.z; p[3] = v.w;
        }
    }
    // load 32x128 features
    {
        const float4* src = (const float4*)(feat + n0 * DD);
        float4* dst = (float4*)&s->f[0][0];
        dst[tid]      = src[tid];
        dst[tid + NT] = src[tid + NT];
    }
    int anyodd = __syncthreads_or(pred);
    int shift = anyodd ? 0 : 1;

    if (tid < NB) {
        int l = lab32[(n0 + tid) << shift];
        s->lab[tid] = min(max(l, 0), KC - 1);
    }

    // mus squared-norm partials
    {
        int k = tid & 63, q = tid >> 6;
        float sm = 0.0f;
        const float* p = &s->mus[k * MPAD + q * 16];
#pragma unroll
        for (int r = 0; r < 16; r++) { float m = p[r]; sm += m * m; }
        s->musq[q][k] = sm;
    }
    // feature norms: warp w handles rows 2w, 2w+1
    {
        int w = tid >> 5, lane = tid & 31;
#pragma unroll
        for (int rr = 0; rr < 2; rr++) {
            int r = 2 * w + rr;
            float sm = 0.0f;
#pragma unroll
            for (int c = 0; c < 4; c++) {
                float x = s->f[r][lane + 32 * c];
                sm += x * x;
            }
#pragma unroll
            for (int o = 16; o > 0; o >>= 1) sm += __shfl_xor_sync(0xffffffffu, sm, o);
            if (lane == 0) s->invn[r] = 1.0f / fmaxf(sqrtf(sm), 1e-12f);
        }
    }
    __syncthreads();

    // per-class scalars
    if (tid < KC) {
        float sm = 0.0f;
#pragma unroll
        for (int q = 0; q < 8; q++) sm += s->musq[q][tid];
        s->invmu[tid] = 1.0f / fmaxf(sqrtf(sm), 1e-12f);
        float r = rho[tid];
        float kap = fmaxf(softplus_precise(r), 1e-6f);
        s->kap[tid] = kap;
        float logI = (kap < 1e-3f)
                   ? 63.0f * logf(kap * 0.5f + 1e-12f) - LGAMMA64F
                   : kap - 0.5f * logf(6.283185307179586f * kap + 1e-12f);
        s->lc[tid] = -63.0f * logf(kap + 1e-12f) - 64.0f * LOG2PIF - logI;
    }
    if (tid < NB) atomicAdd(&g_counts[s->lab[tid]], 1.0f);
    __syncthreads();

    // L = logC + kappa*invmu*invn*(f . mu_raw); 8 groups x 4 samples, packed f32x2
    int g = tid >> 6;
    int k = tid & 63;
    {
        unsigned long long a0 = 0ull, a1 = 0ull, a2 = 0ull, a3 = 0ull;
        const ulonglong2* m2 = (const ulonglong2*)&s->mus[k * MPAD];
        const ulonglong2* F0 = (const ulonglong2*)&s->f[g * 4 + 0][0];
        const ulonglong2* F1 = (const ulonglong2*)&s->f[g * 4 + 1][0];
        const ulonglong2* F2 = (const ulonglong2*)&s->f[g * 4 + 2][0];
        const ulonglong2* F3 = (const ulonglong2*)&s->f[g * 4 + 3][0];
#pragma unroll
        for (int d4 = 0; d4 < DD / 4; d4++) {
            ulonglong2 mv = m2[d4];
            ulonglong2 x0 = F0[d4], x1 = F1[d4], x2 = F2[d4], x3 = F3[d4];
            fma2(a0, mv.x, x0.x); fma2(a0, mv.y, x0.y);
            fma2(a1, mv.x, x1.x); fma2(a1, mv.y, x1.y);
            fma2(a2, mv.x, x2.x); fma2(a2, mv.y, x2.y);
            fma2(a3, mv.x, x3.x); fma2(a3, mv.y, x3.y);
        }
        float sk = s->kap[k] * s->invmu[k], lc = s->lc[k];
        s->L[g * 4 + 0][k] = lc + sk * s->invn[g * 4 + 0] * hsum2(a0);
        s->L[g * 4 + 1][k] = lc + sk * s->invn[g * 4 + 1] * hsum2(a1);
        s->L[g * 4 + 2][k] = lc + sk * s->invn[g * 4 + 2] * hsum2(a2);
        s->L[g * 4 + 3][k] = lc + sk * s->invn[g * 4 + 3] * hsum2(a3);
    }
    __syncthreads();

    // numer + dsum: thread -> (n = tid>>4, k-quad); two v4 REDG
    {
        int n = tid >> 4;
        int k0 = (tid & 15) * 4;
        float4 Lv  = *(const float4*)&s->L[n][k0];
        float4 lcv = *(const float4*)&s->lc[k0];
        float Li = s->L[n][s->lab[n]];
        float Lr[4] = {Lv.x, Lv.y, Lv.z, Lv.w};
        float lcr[4] = {lcv.x, lcv.y, lcv.z, lcv.w};
        float vn[4], vd[4];
#pragma unroll
        for (int c = 0; c < 4; c++) {
            float x = Lr[c] - Li;
            float t = __expf(-fabsf(x));
            vn[c] = LN2F - (log1p_poly(t) + fmaxf(x, 0.0f));
            vd[c] = Lr[c] - lcr[c];           // kap_j * (fhat . mu_j)
        }
        int row = s->lab[n] * KC + k0;
        red_v4(&g_numer[row], vn[0], vn[1], vn[2], vn[3]);
        red_v4(&g_dsum[row],  vd[0], vd[1], vd[2], vd[3]);
    }

    // ---------------- last-arriver election (no spin) ----------------
    __threadfence();
    __syncthreads();
    if (tid == 0) s->is_last = (atomicAdd(&g_arrive, 1) == GRID - 1);
    __syncthreads();
    if (!s->is_last) return;
    __threadfence();

    // ================ single-block epilogue ================
    float* numr2 = &s->f[0][0];       // [64][64] overlay
    float* dsum2 = &s->mus[0];        // [64][64] overlay
    float* ep    = &s->L[0][0];
    float* ics   = ep + 64;           // 64
    float* Ei    = ep + 128;          // 64
    float* zif   = ep + 192;          // 64
    float* wr    = ep + 256;          // 16
    float* wj    = ep + 272;          // 16

    {
        const float4* gn = (const float4*)g_numer;
        const float4* gd = (const float4*)g_dsum;
        float4* dn = (float4*)numr2;
        float4* dd = (float4*)dsum2;
        dn[tid] = gn[tid]; dn[tid + NT] = gn[tid + NT];
        dd[tid] = gd[tid]; dd[tid + NT] = gd[tid + NT];
    }
    int zpred = 0;
    if (tid < KC) {
        float c = g_counts[tid];
        ics[tid] = 1.0f / fmaxf(c, 1.0f);
        zif[tid] = (c == 0.0f) ? 1.0f : 0.0f;
        zpred = (c == 0.0f);
    }
    int anyzero = __syncthreads_or(zpred);

    if (tid < KC)
        Ei[tid] = (zif[tid] != 0.0f) ? s->kap[tid] : dsum2[tid * KC + tid] * ics[tid];
    {
        float4 z4 = make_float4(0.f, 0.f, 0.f, 0.f);
        float4* gn = (float4*)g_numer;
        float4* gd = (float4*)g_dsum;
        gn[tid] = z4; gn[tid + NT] = z4;
        gd[tid] = z4; gd[tid + NT] = z4;
    }
    if (tid < KC) g_counts[tid] = 0.0f;
    if (tid == 0) g_arrive = 0;
    __syncthreads();

    float r_acc = 0.0f, j_acc = 0.0f;
#pragma unroll
    for (int c = 0; c < 8; c++) {
        int p = tid + NT * c;
        int i = p >> 6, j = p & 63;
        float w = (i == j) ? 0.0f : fabsf((float)(i - j));
        bool zpi = false, zpj = false;
        float du = 0.0f;
        if (anyzero) {
            zpi = (zif[i] != 0.0f);
            zpj = (zif[j] != 0.0f);
            if (zpi || zpj) {
                float dd = 0.0f;
                for (int d = 0; d < DD; d++)
                    dd += musp[i * DD + d] * musp[j * DD + d];
                du = dd * s->invmu[i] * s->invmu[j];
            }
        }
        float diff = zpi ? (s->kap[i] - s->kap[j] * du)
                         : (Ei[i] - dsum2[i * KC + j] * ics[i]);
        if (i != j) r_acc += fmaxf(0.5f * w - diff, 0.0f) * ics[i];
        if (zpi || zpj) {
            float ki = s->kap[i], kj = s->kap[j];
            float kci = fmaxf(ki, 1e-8f), kcj = fmaxf(kj, 1e-8f);
            float Ai = (kci > 50.0f) ? (1.0f - 127.0f / (2.0f * kci)) : (kci / 128.0f);
            float Aj = (kcj > 50.0f) ? (1.0f - 127.0f / (2.0f * kcj)) : (kcj / 128.0f);
            j_acc += w * 0.5f * (Ai * (ki - kj * du) + Aj * (kj - ki * du));
        } else {
            j_acc += w * numr2[i * KC + j] * ics[i];
        }
    }

    int wid = tid >> 5, lane = tid & 31;
#pragma unroll
    for (int o = 16; o > 0; o >>= 1) {
        r_acc += __shfl_xor_sync(0xffffffffu, r_acc, o);
        j_acc += __shfl_xor_sync(0xffffffffu, j_acc, o);
    }
    if (lane == 0) { wr[wid] = r_acc; wj[wid] = j_acc; }
    __syncthreads();
    if (tid < 16) {
        float r = wr[tid], jj = wj[tid];
#pragma unroll
        for (int o = 8; o > 0; o >>= 1) {
            r  += __shfl_xor_sync(0xffffu, r, o);
            jj += __shfl_xor_sync(0xffffu, jj, o);
        }
        if (tid == 0)
            out[0] = r / (4096.0f + 1e-9f) + jj / (87360.0f + 1e-9f);
    }
}

extern "C" void kernel_launch(void* const* d_in, const int* in_sizes, int n_in,
                              void* d_out, int out_size) {
    const float* features  = (const float*)d_in[0];
    const float* mus_param = (const float*)d_in[1];
    const float* rho_kappa = (const float*)d_in[2];
    const int*   labels32  = (const int*)d_in[3];
    float* out = (float*)d_out;

    cudaFuncSetAttribute(k_fused, cudaFuncAttributeMaxDynamicSharedMemorySize,
                         (int)sizeof(Smem));
    k_fused<<<GRID, NT, sizeof(Smem)>>>(features, mus_param, rho_kappa, labels32, out);
}

// round 15
// speedup vs baseline: 1.0042x; 1.0042x over previous
#include <cuda_runtime.h>
#include <cuda_bf16.h>
#include <math.h>

#define KC 64
#define DD 128
#define NN 4096
#define NB 32
#define NT 512
#define GRID (NN / NB)   // 128 blocks: one per SM, single balanced wave
#define MPAD 132         // 16B-aligned rows

#define LN2F 0.6931471805599453f
#define LOG2PIF 1.8378770664093453f
#define LGAMMA64F 201.00931639928152f

// ---------------- device scratch (zero-init; self-resetting each run) ----------------
__device__ __align__(16) float g_numer[KC * KC];   // sum of (ln2 - softplus)
__device__ __align__(16) float g_dsum[KC * KC];    // sum over class i of kap_j*(fhat.mu_j)
__device__ float g_counts[KC];
__device__ int   g_arrive;

__device__ __forceinline__ float softplus_precise(float x) {
    return (x > 0.0f) ? (x + log1pf(expf(-x))) : log1pf(expf(x));
}

// log1p(t), t in [0,1]: Taylor at t=0.5, deg 11, |err| < 2e-7. Pure FFMA.
__device__ __forceinline__ float log1p_poly(float t) {
    float s = t - 0.5f;
    float p = -0.0017337974f + 0.0010507863f * s;
    p = fmaf(p, s,  0.0028896624f);
    p = fmaf(p, s, -0.0048773053f);
    p = fmaf(p, s,  0.0083610948f);
    p = fmaf(p, s, -0.0146319159f);
    p = fmaf(p, s,  0.0263374486f);
    p = fmaf(p, s, -0.0493827160f);
    p = fmaf(p, s,  0.0987654321f);
    p = fmaf(p, s, -0.2222222222f);
    p = fmaf(p, s,  0.6666666667f);
    p = fmaf(p, s,  0.4054651081f);
    return p;
}

__device__ __forceinline__ void red_v4(float* gptr, float a, float b, float c, float d) {
    unsigned long long ga = (unsigned long long)__cvta_generic_to_global(gptr);
    asm volatile("red.global.add.v4.f32 [%0], {%1, %2, %3, %4};"
                 :: "l"(ga), "f"(a), "f"(b), "f"(c), "f"(d) : "memory");
}

// packed dual-FMA: d = a*b + d on two f32 lanes (sm_100+)
__device__ __forceinline__ void fma2(unsigned long long& d,
                                     unsigned long long a, unsigned long long b) {
    asm("fma.rn.f32x2 %0, %1, %2, %0;" : "+l"(d) : "l"(a), "l"(b));
}
__device__ __forceinline__ float hsum2(unsigned long long v) {
    float lo, hi;
    asm("mov.b64 {%0, %1}, %2;" : "=f"(lo), "=f"(hi) : "l"(v));
    return lo + hi;
}

struct __align__(16) Smem {
    float mus[KC * MPAD];        // raw mus — epilogue dsum overlay (first 16KB)
    float f[NB][DD];             // features (16KB) — epilogue numer overlay
    float L[NB][KC];             // logits (8KB)    — epilogue scratch
    float lc[KC];
    float invmu[KC], kap[KC];
    float invn[NB];
    int   lab[NB];
    int   is_last;
};

__global__ void __launch_bounds__(NT, 1) k_fused(const float* __restrict__ feat,
                                                 const float* __restrict__ musp,
                                                 const float* __restrict__ rho,
                                                 const int* __restrict__ lab32,
                                                 float* __restrict__ out) {
    extern __shared__ char smem_raw[];
    Smem* s = (Smem*)smem_raw;
    int tid = threadIdx.x;
    int bid = blockIdx.x;
    int n0 = bid * NB;

    // labels dtype probe (odd int32 words nonzero => int32 labels)
    int pred = (lab32[2 * tid + 1] != 0);

    // load mus_param coalesced -> padded rows
    {
        const float4* msrc = (const float4*)musp;
#pragma unroll
        for (int r = 0; r < 4; r++) {
            int idx = tid + NT * r;
            float4 v = msrc[idx];
            int k = idx >> 5, d = (idx & 31) * 4;
            float* p = &s->mus[k * MPAD + d];
            p[0] = v.x; p[1] = v.y; p[2] = v.z; p[3] = v.w;
        }
    }
    // load 32x128 features
    {
        const float4* src = (const float4*)(feat + n0 * DD);
        float4* dst = (float4*)&s->f[0][0];
        dst[tid]      = src[tid];
        dst[tid + NT] = src[tid + NT];
    }
    int anyodd = __syncthreads_or(pred);            // ---- block barrier 1 ----
    int shift = anyodd ? 0 : 1;

    if (tid < NB) {
        int l = lab32[(n0 + tid) << shift];
        s->lab[tid] = min(max(l, 0), KC - 1);
        atomicAdd(&g_counts[s->lab[tid]], 1.0f);    // drain early
    }

    int g = tid >> 6;        // group 0..7 (2 warps each)
    int k = tid & 63;

    // scalars (kap, lc) on tid<64 — runs CONCURRENTLY with norms+dot below
    if (tid < KC) {
        float r = rho[tid];
        float kap = fmaxf(softplus_precise(r), 1e-6f);
        s->kap[tid] = kap;
        float logI = (kap < 1e-3f)
                   ? 63.0f * logf(kap * 0.5f + 1e-12f) - LGAMMA64F
                   : kap - 0.5f * logf(6.283185307179586f * kap + 1e-12f);
        s->lc[tid] = -63.0f * logf(kap + 1e-12f) - 64.0f * LOG2PIF - logI;
    }

    // feature norms: warp w handles rows 2w, 2w+1 (rows of its own group)
    {
        int w = tid >> 5, lane = tid & 31;
#pragma unroll
        for (int rr = 0; rr < 2; rr++) {
            int r = 2 * w + rr;
            float sm = 0.0f;
#pragma unroll
            for (int c = 0; c < 4; c++) {
                float x = s->f[r][lane + 32 * c];
                sm += x * x;
            }
#pragma unroll
            for (int o = 16; o > 0; o >>= 1) sm += __shfl_xor_sync(0xffffffffu, sm, o);
            if (lane == 0) s->invn[r] = 1.0f / fmaxf(sqrtf(sm), 1e-12f);
        }
    }

    // dot loop (f32x2) with mu.mu folded in; needs nothing but smem loads
    unsigned long long a0 = 0ull, a1 = 0ull, a2 = 0ull, a3 = 0ull, am = 0ull;
    {
        const ulonglong2* m2 = (const ulonglong2*)&s->mus[k * MPAD];
        const ulonglong2* F0 = (const ulonglong2*)&s->f[g * 4 + 0][0];
        const ulonglong2* F1 = (const ulonglong2*)&s->f[g * 4 + 1][0];
        const ulonglong2* F2 = (const ulonglong2*)&s->f[g * 4 + 2][0];
        const ulonglong2* F3 = (const ulonglong2*)&s->f[g * 4 + 3][0];
#pragma unroll
        for (int d4 = 0; d4 < DD / 4; d4++) {
            ulonglong2 mv = m2[d4];
            ulonglong2 x0 = F0[d4], x1 = F1[d4], x2 = F2[d4], x3 = F3[d4];
            fma2(a0, mv.x, x0.x); fma2(a0, mv.y, x0.y);
            fma2(a1, mv.x, x1.x); fma2(a1, mv.y, x1.y);
            fma2(a2, mv.x, x2.x); fma2(a2, mv.y, x2.y);
            fma2(a3, mv.x, x3.x); fma2(a3, mv.y, x3.y);
            fma2(am, mv.x, mv.x); fma2(am, mv.y, mv.y);
        }
    }
    __syncthreads();                                // ---- block barrier 2 ----

    // finalize L (kap/lc/invn now visible); per-thread invmu
    {
        float invmu = rsqrtf(fmaxf(hsum2(am), 1e-24f));
        if (tid < KC) s->invmu[tid] = invmu;        // for epilogue zero-count path
        float sk = s->kap[k] * invmu, lc = s->lc[k];
        s->L[g * 4 + 0][k] = lc + sk * s->invn[g * 4 + 0] * hsum2(a0);
        s->L[g * 4 + 1][k] = lc + sk * s->invn[g * 4 + 1] * hsum2(a1);
        s->L[g * 4 + 2][k] = lc + sk * s->invn[g * 4 + 2] * hsum2(a2);
        s->L[g * 4 + 3][k] = lc + sk * s->invn[g * 4 + 3] * hsum2(a3);
    }
    // group-local barrier: only this group's 64 threads produced/consume its L rows
    asm volatile("bar.sync %0, 64;" :: "r"(g + 1) : "memory");

    // numer + dsum: thread -> (n in own group, k-quad); two v4 REDG
    {
        int n = g * 4 + ((tid & 63) >> 4);
        int k0 = (tid & 15) * 4;
        float4 Lv  = *(const float4*)&s->L[n][k0];
        float4 lcv = *(const float4*)&s->lc[k0];
        float Li = s->L[n][s->lab[n]];
        float Lr[4] = {Lv.x, Lv.y, Lv.z, Lv.w};
        float lcr[4] = {lcv.x, lcv.y, lcv.z, lcv.w};
        float vn[4], vd[4];
#pragma unroll
        for (int c = 0; c < 4; c++) {
            float x = Lr[c] - Li;
            float t = __expf(-fabsf(x));
            vn[c] = LN2F - (log1p_poly(t) + fmaxf(x, 0.0f));
            vd[c] = Lr[c] - lcr[c];           // kap_j * (fhat . mu_j)
        }
        int row = s->lab[n] * KC + k0;
        red_v4(&g_numer[row], vn[0], vn[1], vn[2], vn[3]);
        red_v4(&g_dsum[row],  vd[0], vd[1], vd[2], vd[3]);
    }

    // ---------------- last-arriver election (no spin) ----------------
    __threadfence();
    __syncthreads();                                // ---- block barrier 3 ----
    if (tid == 0) s->is_last = (atomicAdd(&g_arrive, 1) == GRID - 1);
    __syncthreads();
    if (!s->is_last) return;
    __threadfence();

    // ================ single-block epilogue ================
    float* numr2 = &s->f[0][0];       // [64][64] overlay
    float* dsum2 = &s->mus[0];        // [64][64] overlay
    float* ep    = &s->L[0][0];
    float* ics   = ep + 64;
    float* Ei    = ep + 128;
    float* zif   = ep + 192;
    float* wr    = ep + 256;
    float* wj    = ep + 272;

    {
        const float4* gn = (const float4*)g_numer;
        const float4* gd = (const float4*)g_dsum;
        float4* dn = (float4*)numr2;
        float4* dd = (float4*)dsum2;
        dn[tid] = gn[tid]; dn[tid + NT] = gn[tid + NT];
        dd[tid] = gd[tid]; dd[tid + NT] = gd[tid + NT];
    }
    int zpred = 0;
    if (tid < KC) {
        float c = g_counts[tid];
        ics[tid] = 1.0f / fmaxf(c, 1.0f);
        zif[tid] = (c == 0.0f) ? 1.0f : 0.0f;
        zpred = (c == 0.0f);
    }
    int anyzero = __syncthreads_or(zpred);

    if (tid < KC)
        Ei[tid] = (zif[tid] != 0.0f) ? s->kap[tid] : dsum2[tid * KC + tid] * ics[tid];
    {
        float4 z4 = make_float4(0.f, 0.f, 0.f, 0.f);
        float4* gn = (float4*)g_numer;
        float4* gd = (float4*)g_dsum;
        gn[tid] = z4; gn[tid + NT] = z4;
        gd[tid] = z4; gd[tid + NT] = z4;
    }
    if (tid < KC) g_counts[tid] = 0.0f;
    if (tid == 0) g_arrive = 0;
    __syncthreads();

    float r_acc = 0.0f, j_acc = 0.0f;
#pragma unroll
    for (int c = 0; c < 8; c++) {
        int p = tid + NT * c;
        int i = p >> 6, j = p & 63;
        float w = (i == j) ? 0.0f : fabsf((float)(i - j));
        bool zpi = false, zpj = false;
        float du = 0.0f;
        if (anyzero) {
            zpi = (zif[i] != 0.0f);
            zpj = (zif[j] != 0.0f);
            if (zpi || zpj) {
                float dd = 0.0f;
                for (int d = 0; d < DD; d++)
                    dd += musp[i * DD + d] * musp[j * DD + d];
                du = dd * s->invmu[i] * s->invmu[j];
            }
        }
        float diff = zpi ? (s->kap[i] - s->kap[j] * du)
                         : (Ei[i] - dsum2[i * KC + j] * ics[i]);
        if (i != j) r_acc += fmaxf(0.5f * w - diff, 0.0f) * ics[i];
        if (zpi || zpj) {
            float ki = s->kap[i], kj = s->kap[j];
            float kci = fmaxf(ki, 1e-8f), kcj = fmaxf(kj, 1e-8f);
            float Ai = (kci > 50.0f) ? (1.0f - 127.0f / (2.0f * kci)) : (kci / 128.0f);
            float Aj = (kcj > 50.0f) ? (1.0f - 127.0f / (2.0f * kcj)) : (kcj / 128.0f);
            j_acc += w * 0.5f * (Ai * (ki - kj * du) + Aj * (kj - ki * du));
        } else {
            j_acc += w * numr2[i * KC + j] * ics[i];
        }
    }

    int wid = tid >> 5, lane = tid & 31;
#pragma unroll
    for (int o = 16; o > 0; o >>= 1) {
        r_acc += __shfl_xor_sync(0xffffffffu, r_acc, o);
        j_acc += __shfl_xor_sync(0xffffffffu, j_acc, o);
    }
    if (lane == 0) { wr[wid] = r_acc; wj[wid] = j_acc; }
    __syncthreads();
    if (tid < 16) {
        float r = wr[tid], jj = wj[tid];
#pragma unroll
        for (int o = 8; o > 0; o >>= 1) {
            r  += __shfl_xor_sync(0xffffu, r, o);
            jj += __shfl_xor_sync(0xffffu, jj, o);
        }
        if (tid == 0)
            out[0] = r / (4096.0f + 1e-9f) + jj / (87360.0f + 1e-9f);
    }
}

extern "C" void kernel_launch(void* const* d_in, const int* in_sizes, int n_in,
                              void* d_out, int out_size) {
    const float* features  = (const float*)d_in[0];
    const float* mus_param = (const float*)d_in[1];
    const float* rho_kappa = (const float*)d_in[2];
    const int*   labels32  = (const int*)d_in[3];
    float* out = (float*)d_out;

    cudaFuncSetAttribute(k_fused, cudaFuncAttributeMaxDynamicSharedMemorySize,
                         (int)sizeof(Smem));
    k_fused<<<GRID, NT, sizeof(Smem)>>>(features, mus_param, rho_kappa, labels32, out);
}